// round 3
// baseline (speedup 1.0000x reference)
#include <cuda_runtime.h>
#include <cuda_bf16.h>
#include <math.h>

// Problem constants
#define N0 200000
#define N1 50000
#define N2 10000
#define D_IN 128
#define D_PROMPT 64
#define D_HID 256
#define E0 800000
#define E1 160000

// ---------------- scratch (static device globals; no allocation) ----------------
__device__ float g_P[N0 * D_PROMPT];         // selected prompt, relu'd   [200000,64]
__device__ float g_aggf[N1 * D_IN];          // mean-agg features (scaled)[50000,128]
__device__ float g_aggp[N1 * D_PROMPT];      // mean-agg prompt  (scaled) [50000,64]
__device__ float g_H1[N1 * D_HID];           // layer0 output             [50000,256]
__device__ float g_z1[N1 * 2];               // H1 @ wn1c                 [50000,2]
__device__ float g_z1acc[N2 * 2];            // segment-sum of z1         [10000,2]
__device__ float g_deg1[N2];                 // layer1 in-degree
__device__ int   g_hist[N1];                 // layer0 in-degree histogram
__device__ int   g_rowstart[N1 + 1];         // CSR offsets
__device__ int   g_cursor[N1];               // scatter cursors
__device__ int   g_esrc[E0];                 // src node per CSR slot
__device__ float g_wn1c[D_HID * 2];          // w_neigh1 @ w_cls
__device__ float g_ws1c[D_HID * 2];          // w_self1 @ w_cls
__device__ float g_bc[2];                    // b1 @ w_cls + b_cls
__device__ int   g_maskIs8;                  // 1 if mask is packed uint8, 0 if int32

// ---------------- small utility kernels ----------------
__global__ void k_zero() {
    int i = blockIdx.x * blockDim.x + threadIdx.x;
    if (i < N1) g_hist[i] = 0;
    if (i < N2 * 2) g_z1acc[i] = 0.0f;
    if (i < N2) g_deg1[i] = 0.0f;
    if (i == 0) g_maskIs8 = 0;
}

// Detect mask dtype: scan first 50000 words (safe for both uint8[200000] and
// int32[200000] layouts). int32 bool -> every word is 0 or 1. Packed uint8
// bools -> words with multiple nonzero bytes (>1) appear w.h.p.
__global__ void k_detect(const unsigned int* __restrict__ maskw) {
    int i = blockIdx.x * blockDim.x + threadIdx.x;
    if (i < N0 / 4) {
        if (maskw[i] > 1u) atomicOr(&g_maskIs8, 1);
    }
}

__global__ void k_hist(const int* __restrict__ dst0) {
    int e = blockIdx.x * blockDim.x + threadIdx.x;
    if (e < E0) atomicAdd(&g_hist[dst0[e]], 1);
}

__global__ void k_scan() {
    __shared__ int ssum[1024];
    __shared__ int s_carry;
    int tid = threadIdx.x;
    if (tid == 0) s_carry = 0;
    for (int base = 0; base < N1; base += 8192) {
        __syncthreads();
        int c = s_carry;
        int idx0 = base + tid * 8;
        int v[8];
        int local = 0;
#pragma unroll
        for (int j = 0; j < 8; ++j) {
            int x = (idx0 + j < N1) ? g_hist[idx0 + j] : 0;
            v[j] = local;
            local += x;
        }
        ssum[tid] = local;
        __syncthreads();
        for (int off = 1; off < 1024; off <<= 1) {
            int t = (tid >= off) ? ssum[tid - off] : 0;
            __syncthreads();
            ssum[tid] += t;
            __syncthreads();
        }
        int excl = ssum[tid] - local;
#pragma unroll
        for (int j = 0; j < 8; ++j) {
            int idx = idx0 + j;
            if (idx < N1) {
                int rs = c + excl + v[j];
                g_rowstart[idx] = rs;
                g_cursor[idx] = rs;
            }
        }
        __syncthreads();
        if (tid == 1023) s_carry = c + ssum[1023];
    }
    __syncthreads();
    if (tid == 0) g_rowstart[N1] = s_carry;
}

__global__ void k_scatter(const int* __restrict__ src0, const int* __restrict__ dst0) {
    int e = blockIdx.x * blockDim.x + threadIdx.x;
    if (e < E0) {
        int pos = atomicAdd(&g_cursor[dst0[e]], 1);
        g_esrc[pos] = src0[e];
    }
}

// fold layer1 + classifier weights: wn1c = w_neigh1 @ w_cls, ws1c = w_self1 @ w_cls
__global__ void k_prep(const float* __restrict__ wself1, const float* __restrict__ wneigh1,
                       const float* __restrict__ b1, const float* __restrict__ wcls,
                       const float* __restrict__ bcls) {
    int k = threadIdx.x;  // 0..255
    float a0 = 0.f, a1 = 0.f, s0 = 0.f, s1 = 0.f;
    for (int m = 0; m < D_HID; ++m) {
        float c0 = wcls[2 * m], c1 = wcls[2 * m + 1];
        float wn = wneigh1[k * D_HID + m];
        float ws = wself1[k * D_HID + m];
        a0 += wn * c0; a1 += wn * c1;
        s0 += ws * c0; s1 += ws * c1;
    }
    g_wn1c[2 * k] = a0; g_wn1c[2 * k + 1] = a1;
    g_ws1c[2 * k] = s0; g_ws1c[2 * k + 1] = s1;
    if (k < 2) {
        float acc = 0.f;
        for (int m = 0; m < D_HID; ++m) acc += b1[m] * wcls[2 * m + k];
        g_bc[k] = acc + bcls[k];
    }
}

// mask accessor: handles int32 (default) or packed uint8 layout
__device__ __forceinline__ bool read_mask(const void* mask, int r) {
    if (g_maskIs8) return ((const unsigned char*)mask)[r] != 0;
    return ((const int*)mask)[r] != 0;
}

// ---------------- prompt GEMM: Y = X @ [Wpin | Wpout], select+relu epilogue ----------------
__global__ void __launch_bounds__(256) k_prompt(
    const float* __restrict__ X, const void* __restrict__ mask,
    const float* __restrict__ wpin, const float* __restrict__ bpin,
    const float* __restrict__ wpout, const float* __restrict__ bpout) {
    __shared__ float As[64 * 64];
    __shared__ float Bs[64 * 128];
    int tid = threadIdx.x;
    int tr = tid >> 5;   // warp 0..7 -> rows tr*8..+8
    int tc = tid & 31;   // -> cols tc*4..+4
    int rowBase = blockIdx.x * 64;
    float acc[8][4];
#pragma unroll
    for (int i = 0; i < 8; ++i)
#pragma unroll
        for (int j = 0; j < 4; ++j) acc[i][j] = 0.f;

    for (int kb = 0; kb < 2; ++kb) {
        // A tile: 64 rows x 64 k
#pragma unroll
        for (int p = 0; p < 4; ++p) {
            int qi = tid + 256 * p;
            int r = qi >> 4, qc = qi & 15;
            float4 v = *(const float4*)&X[(size_t)(rowBase + r) * D_IN + kb * 64 + qc * 4];
            *(float4*)&As[r * 64 + qc * 4] = v;
        }
        // B tile: 64 k x 128 n (cols 0..63 = wpin, 64..127 = wpout)
        {
            int nv = tid & 31;
            int k0 = tid >> 5;
            int n = nv * 4;
            const float* src = (n < 64) ? wpin : wpout;
            int ncol = (n < 64) ? n : n - 64;
#pragma unroll
            for (int p = 0; p < 8; ++p) {
                int k = k0 + p * 8;
                float4 v = *(const float4*)&src[(kb * 64 + k) * 64 + ncol];
                *(float4*)&Bs[k * 128 + n] = v;
            }
        }
        __syncthreads();
#pragma unroll 8
        for (int k = 0; k < 64; ++k) {
            float a[8];
#pragma unroll
            for (int i = 0; i < 8; ++i) a[i] = As[(tr * 8 + i) * 64 + k];
            float4 b = *(const float4*)&Bs[k * 128 + tc * 4];
#pragma unroll
            for (int i = 0; i < 8; ++i) {
                acc[i][0] += a[i] * b.x;
                acc[i][1] += a[i] * b.y;
                acc[i][2] += a[i] * b.z;
                acc[i][3] += a[i] * b.w;
            }
        }
        __syncthreads();
    }
    // epilogue: select half by mask, +bias, relu, write P
    int c0 = tc * 4;
    bool inHalf = (c0 < 64);  // true => this thread holds p_in columns
    float bias[4];
#pragma unroll
    for (int j = 0; j < 4; ++j) bias[j] = inHalf ? bpin[c0 + j] : bpout[c0 - 64 + j];
#pragma unroll
    for (int i = 0; i < 8; ++i) {
        int r = rowBase + tr * 8 + i;
        bool m = read_mask(mask, r);
        if (m == inHalf) {
            int cc = inHalf ? c0 : (c0 - 64);
            float4 o;
            o.x = fmaxf(acc[i][0] + bias[0], 0.f);
            o.y = fmaxf(acc[i][1] + bias[1], 0.f);
            o.z = fmaxf(acc[i][2] + bias[2], 0.f);
            o.w = fmaxf(acc[i][3] + bias[3], 0.f);
            *(float4*)&g_P[(size_t)r * D_PROMPT + cc] = o;
        }
    }
}

// ---------------- layer0 CSR gather: mean of [features|P] rows into agg (pre-scaled) ----------------
__global__ void __launch_bounds__(256) k_gather0(const float* __restrict__ features) {
    int gw = (blockIdx.x * 256 + threadIdx.x) >> 5;  // dst row, warp per row
    int lane = threadIdx.x & 31;
    if (gw >= N1) return;
    int s0 = g_rowstart[gw], s1 = g_rowstart[gw + 1];
    const float4* F4 = (const float4*)features;  // 32 quads per row
    const float2* P2 = (const float2*)g_P;       // 32 pairs per row
    float4 af = make_float4(0.f, 0.f, 0.f, 0.f);
    float2 ap = make_float2(0.f, 0.f);
    for (int t = s0; t < s1; ++t) {
        int s = g_esrc[t];
        float4 f = F4[(size_t)s * 32 + lane];
        af.x += f.x; af.y += f.y; af.z += f.z; af.w += f.w;
        float2 p = P2[(size_t)s * 32 + lane];
        ap.x += p.x; ap.y += p.y;
    }
    float inv = 1.0f / fmaxf((float)(s1 - s0), 1.0f);
    float4 of = make_float4(af.x * inv, af.y * inv, af.z * inv, af.w * inv);
    ((float4*)g_aggf)[(size_t)gw * 32 + lane] = of;
    float2 op = make_float2(ap.x * inv, ap.y * inv);
    ((float2*)g_aggp)[(size_t)gw * 32 + lane] = op;
}

// ---------------- layer0 GEMM: H1 = relu([f|P|aggf|aggp] @ [wself0;wneigh0] + b0) ----------------
__global__ void __launch_bounds__(256) k_layer0(
    const float* __restrict__ features, const float* __restrict__ wself,
    const float* __restrict__ wneigh, const float* __restrict__ b0) {
    __shared__ float As[64 * 64];
    __shared__ float Bs[64 * 128];
    int tid = threadIdx.x;
    int tr = tid >> 5;
    int tc = tid & 31;
    int rowBase = blockIdx.x * 64;
    int colBase = blockIdx.y * 128;
    const float4* F4 = (const float4*)features;
    const float4* P4 = (const float4*)g_P;
    const float4* AF4 = (const float4*)g_aggf;
    const float4* AP4 = (const float4*)g_aggp;
    float acc[8][4];
#pragma unroll
    for (int i = 0; i < 8; ++i)
#pragma unroll
        for (int j = 0; j < 4; ++j) acc[i][j] = 0.f;

    for (int kb = 0; kb < 6; ++kb) {
        // A tile (virtual concat over K = 384)
#pragma unroll
        for (int p = 0; p < 4; ++p) {
            int qi = tid + 256 * p;
            int r = qi >> 4, qc = qi & 15;
            int grow = rowBase + r;
            float4 v = make_float4(0.f, 0.f, 0.f, 0.f);
            if (grow < N1) {
                if (kb == 0)      v = F4[(size_t)grow * 32 + qc];
                else if (kb == 1) v = F4[(size_t)grow * 32 + 16 + qc];
                else if (kb == 2) v = P4[(size_t)grow * 16 + qc];
                else if (kb == 3) v = AF4[(size_t)grow * 32 + qc];
                else if (kb == 4) v = AF4[(size_t)grow * 32 + 16 + qc];
                else              v = AP4[(size_t)grow * 16 + qc];
            }
            *(float4*)&As[r * 64 + qc * 4] = v;
        }
        // B tile (stacked weights, K rows 0..191 self, 192..383 neigh)
        {
            int nv = tid & 31;
            int k0 = tid >> 5;
            int n = colBase + nv * 4;
#pragma unroll
            for (int p = 0; p < 8; ++p) {
                int k = k0 + p * 8;
                int gk = kb * 64 + k;
                const float* w = (gk < 192) ? wself : wneigh;
                int wr = (gk < 192) ? gk : gk - 192;
                float4 v = *(const float4*)&w[(size_t)wr * D_HID + n];
                *(float4*)&Bs[k * 128 + nv * 4] = v;
            }
        }
        __syncthreads();
#pragma unroll 8
        for (int k = 0; k < 64; ++k) {
            float a[8];
#pragma unroll
            for (int i = 0; i < 8; ++i) a[i] = As[(tr * 8 + i) * 64 + k];
            float4 b = *(const float4*)&Bs[k * 128 + tc * 4];
#pragma unroll
            for (int i = 0; i < 8; ++i) {
                acc[i][0] += a[i] * b.x;
                acc[i][1] += a[i] * b.y;
                acc[i][2] += a[i] * b.z;
                acc[i][3] += a[i] * b.w;
            }
        }
        __syncthreads();
    }
    int cg = colBase + tc * 4;
    float4 bias = *(const float4*)&b0[cg];
#pragma unroll
    for (int i = 0; i < 8; ++i) {
        int r = rowBase + tr * 8 + i;
        if (r < N1) {
            float4 o;
            o.x = fmaxf(acc[i][0] + bias.x, 0.f);
            o.y = fmaxf(acc[i][1] + bias.y, 0.f);
            o.z = fmaxf(acc[i][2] + bias.z, 0.f);
            o.w = fmaxf(acc[i][3] + bias.w, 0.f);
            *(float4*)&g_H1[(size_t)r * D_HID + cg] = o;
        }
    }
}

// ---------------- z1 = H1 @ wn1c  ([50000,256] @ [256,2]) ----------------
__global__ void __launch_bounds__(256) k_z1() {
    int r = (blockIdx.x * 256 + threadIdx.x) >> 5;
    int lane = threadIdx.x & 31;
    if (r >= N1) return;
    const float4* H4 = (const float4*)g_H1;
    const float2* W2 = (const float2*)g_wn1c;
    float a0 = 0.f, a1 = 0.f;
#pragma unroll
    for (int s = 0; s < 2; ++s) {
        int q = lane + 32 * s;
        float4 h = H4[(size_t)r * 64 + q];
        int k = q * 4;
        float2 w0 = W2[k], w1 = W2[k + 1], w2 = W2[k + 2], w3 = W2[k + 3];
        a0 += h.x * w0.x + h.y * w1.x + h.z * w2.x + h.w * w3.x;
        a1 += h.x * w0.y + h.y * w1.y + h.z * w2.y + h.w * w3.y;
    }
#pragma unroll
    for (int off = 16; off > 0; off >>= 1) {
        a0 += __shfl_xor_sync(0xffffffffu, a0, off);
        a1 += __shfl_xor_sync(0xffffffffu, a1, off);
    }
    if (lane == 0) {
        g_z1[2 * r] = a0;
        g_z1[2 * r + 1] = a1;
    }
}

// ---------------- layer1 edge aggregation on z1 (2 floats/edge) ----------------
__global__ void k_edge1(const int* __restrict__ src1, const int* __restrict__ dst1) {
    int e = blockIdx.x * blockDim.x + threadIdx.x;
    if (e < E1) {
        int s = src1[e], d = dst1[e];
        atomicAdd(&g_z1acc[2 * d], g_z1[2 * s]);
        atomicAdd(&g_z1acc[2 * d + 1], g_z1[2 * s + 1]);
        atomicAdd(&g_deg1[d], 1.0f);
    }
}

// ---------------- final: logits = H1[:N2]@ws1c + z1acc/deg + bc ----------------
__global__ void __launch_bounds__(256) k_final(float* __restrict__ out) {
    int r = (blockIdx.x * 256 + threadIdx.x) >> 5;
    int lane = threadIdx.x & 31;
    if (r >= N2) return;
    const float4* H4 = (const float4*)g_H1;
    const float2* W2 = (const float2*)g_ws1c;
    float a0 = 0.f, a1 = 0.f;
#pragma unroll
    for (int s = 0; s < 2; ++s) {
        int q = lane + 32 * s;
        float4 h = H4[(size_t)r * 64 + q];
        int k = q * 4;
        float2 w0 = W2[k], w1 = W2[k + 1], w2 = W2[k + 2], w3 = W2[k + 3];
        a0 += h.x * w0.x + h.y * w1.x + h.z * w2.x + h.w * w3.x;
        a1 += h.x * w0.y + h.y * w1.y + h.z * w2.y + h.w * w3.y;
    }
#pragma unroll
    for (int off = 16; off > 0; off >>= 1) {
        a0 += __shfl_xor_sync(0xffffffffu, a0, off);
        a1 += __shfl_xor_sync(0xffffffffu, a1, off);
    }
    if (lane == 0) {
        float inv = 1.0f / fmaxf(g_deg1[r], 1.0f);
        out[2 * r] = a0 + g_z1acc[2 * r] * inv + g_bc[0];
        out[2 * r + 1] = a1 + g_z1acc[2 * r + 1] * inv + g_bc[1];
    }
}

// ---------------- launch ----------------
extern "C" void kernel_launch(void* const* d_in, const int* in_sizes, int n_in,
                              void* d_out, int out_size) {
    const float* features = (const float*)d_in[0];
    const void* mask = d_in[1];
    const int* src0 = (const int*)d_in[2];
    const int* dst0 = (const int*)d_in[3];
    const int* src1 = (const int*)d_in[4];
    const int* dst1 = (const int*)d_in[5];
    // d_in[6] = output_nodes_indices (unused by reference)
    const float* w_pin = (const float*)d_in[7];
    const float* b_pin = (const float*)d_in[8];
    const float* w_pout = (const float*)d_in[9];
    const float* b_pout = (const float*)d_in[10];
    const float* w_self0 = (const float*)d_in[11];
    const float* w_neigh0 = (const float*)d_in[12];
    const float* b0 = (const float*)d_in[13];
    const float* w_self1 = (const float*)d_in[14];
    const float* w_neigh1 = (const float*)d_in[15];
    const float* b1 = (const float*)d_in[16];
    const float* w_cls = (const float*)d_in[17];
    const float* b_cls = (const float*)d_in[18];
    float* out = (float*)d_out;

    k_zero<<<196, 256>>>();
    k_detect<<<(N0 / 4 + 255) / 256, 256>>>((const unsigned int*)mask);
    k_hist<<<E0 / 256, 256>>>(dst0);
    k_scan<<<1, 1024>>>();
    k_scatter<<<E0 / 256, 256>>>(src0, dst0);
    k_prep<<<1, 256>>>(w_self1, w_neigh1, b1, w_cls, b_cls);
    k_prompt<<<N0 / 64, 256>>>(features, mask, w_pin, b_pin, w_pout, b_pout);
    k_gather0<<<N1 / 8, 256>>>(features);
    k_layer0<<<dim3((N1 + 63) / 64, 2), 256>>>(features, w_self0, w_neigh0, b0);
    k_z1<<<N1 / 8, 256>>>();
    k_edge1<<<E1 / 256, 256>>>(src1, dst1);
    k_final<<<N2 / 8, 256>>>(out);
}

// round 6
// speedup vs baseline: 1.9039x; 1.9039x over previous
#include <cuda_runtime.h>
#include <cuda_bf16.h>
#include <math.h>
#include <stdint.h>

// Problem constants
#define N0 200000
#define N1 50000
#define N2 10000
#define D_IN 128
#define D_PROMPT 64
#define D_HID 256
#define E0 800000
#define E1 160000

// ---------------- scratch (static device globals; no allocation) ----------------
__device__ float g_P[N0 * D_PROMPT];         // selected prompt, relu'd   [200000,64]
__device__ float g_aggf[N1 * D_IN];          // mean-agg features (scaled)[50000,128]
__device__ float g_aggp[N1 * D_PROMPT];      // mean-agg prompt  (scaled) [50000,64]
__device__ float g_z1[N1 * 2];               // relu(H1) @ wn1c           [50000,2]
__device__ float g_selfc[N2 * 2];            // relu(H1)[:N2] @ ws1c      [10000,2]
__device__ float g_z1acc[N2 * 2];            // segment-sum of z1         [10000,2]
__device__ float g_deg1[N2];                 // layer1 in-degree
__device__ int   g_hist[N1];                 // layer0 in-degree histogram
__device__ int   g_rowstart[N1 + 1];         // CSR offsets
__device__ int   g_cursor[N1];               // scatter cursors
__device__ int   g_esrc[E0];                 // src node per CSR slot
__device__ float g_wn1c[D_HID * 2];          // w_neigh1 @ w_cls
__device__ float g_ws1c[D_HID * 2];          // w_self1 @ w_cls
__device__ float g_bc[2];                    // b1 @ w_cls + b_cls
__device__ int   g_maskIs8;                  // 1 if mask is packed uint8, 0 if int32
__device__ float g_Bp[128 * 128];            // prompt B transposed: [n,k]; n<64 = wpin
__device__ float g_Bl[256 * 384];            // layer0 B transposed+stacked: [n,k]

// ================= mma.sync helpers (baseline PTX, no sm_103a gate) =================
__device__ __forceinline__ uint32_t smem_u32(const void* p) {
    return (uint32_t)__cvta_generic_to_shared(p);
}
__device__ __forceinline__ void ldm_x4(uint32_t* r, uint32_t addr) {
    asm volatile("ldmatrix.sync.aligned.m8n8.x4.shared.b16 {%0,%1,%2,%3}, [%4];"
                 : "=r"(r[0]), "=r"(r[1]), "=r"(r[2]), "=r"(r[3]) : "r"(addr));
}
__device__ __forceinline__ void mma_bf16(float* c, const uint32_t* a, uint32_t b0, uint32_t b1) {
    asm volatile(
        "mma.sync.aligned.m16n8k16.row.col.f32.bf16.bf16.f32 "
        "{%0,%1,%2,%3}, {%4,%5,%6,%7}, {%8,%9}, {%0,%1,%2,%3};"
        : "+f"(c[0]), "+f"(c[1]), "+f"(c[2]), "+f"(c[3])
        : "r"(a[0]), "r"(a[1]), "r"(a[2]), "r"(a[3]), "r"(b0), "r"(b1));
}
// tile rows = 128B (64 bf16), 16B granules XOR-swizzled by row
__device__ __forceinline__ uint32_t tile_addr(uint32_t base, int r, int g) {
    return base + (uint32_t)(r * 128) + (uint32_t)(((g ^ (r & 7)) << 4));
}

__device__ __forceinline__ uint32_t pack_bf2(__nv_bfloat16 a, __nv_bfloat16 b) {
    return ((uint32_t)__bfloat16_as_ushort(b) << 16) | (uint32_t)__bfloat16_as_ushort(a);
}
// fp32 -> (hi bf16, lo bf16) split tile fill; rows of 64 k-values (128B), swizzled
__device__ __forceinline__ void fill_tile(char* hi, char* lo,
                                          const float* __restrict__ src, int stride, int colOfs,
                                          int rowBase, int rowMax, int nRows) {
    for (int i = threadIdx.x; i < nRows * 8; i += 256) {
        int r = i >> 3, g = i & 7;
        int gr = rowBase + r;
        float4 v0 = make_float4(0.f, 0.f, 0.f, 0.f), v1 = v0;
        if (gr < rowMax) {
            const float* p = &src[(size_t)gr * stride + colOfs + g * 8];
            v0 = *(const float4*)p;
            v1 = *(const float4*)(p + 4);
        }
        __nv_bfloat16 h0 = __float2bfloat16_rn(v0.x), h1 = __float2bfloat16_rn(v0.y);
        __nv_bfloat16 h2 = __float2bfloat16_rn(v0.z), h3 = __float2bfloat16_rn(v0.w);
        __nv_bfloat16 h4 = __float2bfloat16_rn(v1.x), h5 = __float2bfloat16_rn(v1.y);
        __nv_bfloat16 h6 = __float2bfloat16_rn(v1.z), h7 = __float2bfloat16_rn(v1.w);
        uint4 H, L;
        H.x = pack_bf2(h0, h1); H.y = pack_bf2(h2, h3);
        H.z = pack_bf2(h4, h5); H.w = pack_bf2(h6, h7);
        L.x = pack_bf2(__float2bfloat16_rn(v0.x - __bfloat162float(h0)),
                       __float2bfloat16_rn(v0.y - __bfloat162float(h1)));
        L.y = pack_bf2(__float2bfloat16_rn(v0.z - __bfloat162float(h2)),
                       __float2bfloat16_rn(v0.w - __bfloat162float(h3)));
        L.z = pack_bf2(__float2bfloat16_rn(v1.x - __bfloat162float(h4)),
                       __float2bfloat16_rn(v1.y - __bfloat162float(h5)));
        L.w = pack_bf2(__float2bfloat16_rn(v1.z - __bfloat162float(h6)),
                       __float2bfloat16_rn(v1.w - __bfloat162float(h7)));
        uint32_t off = (uint32_t)(r * 128) + (uint32_t)(((g ^ (r & 7)) << 4));
        *(uint4*)(hi + off) = H;
        *(uint4*)(lo + off) = L;
    }
}

// ---------------- small utility kernels ----------------
__global__ void k_zero() {
    int i = blockIdx.x * blockDim.x + threadIdx.x;
    if (i < N1) g_hist[i] = 0;
    if (i < N2 * 2) g_z1acc[i] = 0.0f;
    if (i < N2) g_deg1[i] = 0.0f;
    if (i == 0) g_maskIs8 = 0;
}

__global__ void k_detect(const unsigned int* __restrict__ maskw) {
    int i = blockIdx.x * blockDim.x + threadIdx.x;
    if (i < N0 / 4) {
        if (maskw[i] > 1u) atomicOr(&g_maskIs8, 1);
    }
}

__global__ void k_hist(const int* __restrict__ dst0) {
    int e = blockIdx.x * blockDim.x + threadIdx.x;
    if (e < E0) atomicAdd(&g_hist[dst0[e]], 1);
}

// serial-chunk + warp-shuffle scan: 1 block, 1024 threads, 49 elems/thread
__global__ void k_scan() {
    const int CH = 49;  // 1024*49 = 50176 >= N1
    int tid = threadIdx.x, lane = tid & 31, w = tid >> 5;
    int base = tid * CH;
    int s = 0;
    for (int j = 0; j < CH; ++j) {
        int idx = base + j;
        if (idx < N1) s += g_hist[idx];
    }
    int v = s;
#pragma unroll
    for (int off = 1; off < 32; off <<= 1) {
        int t = __shfl_up_sync(0xffffffffu, v, off);
        if (lane >= off) v += t;
    }
    __shared__ int wsum[32];
    if (lane == 31) wsum[w] = v;
    __syncthreads();
    if (w == 0) {
        int x = wsum[lane];
#pragma unroll
        for (int off = 1; off < 32; off <<= 1) {
            int t = __shfl_up_sync(0xffffffffu, x, off);
            if (lane >= off) x += t;
        }
        wsum[lane] = x;
    }
    __syncthreads();
    int run = v - s + (w ? wsum[w - 1] : 0);
    for (int j = 0; j < CH; ++j) {
        int idx = base + j;
        if (idx < N1) {
            g_rowstart[idx] = run;
            g_cursor[idx] = run;
            run += g_hist[idx];
        } else if (idx == N1) {
            g_rowstart[N1] = run;
        }
    }
}

__global__ void k_scatter(const int* __restrict__ src0, const int* __restrict__ dst0) {
    int e = blockIdx.x * blockDim.x + threadIdx.x;
    if (e < E0) {
        int pos = atomicAdd(&g_cursor[dst0[e]], 1);
        g_esrc[pos] = src0[e];
    }
}

// fold layer1 + classifier weights
__global__ void k_prep(const float* __restrict__ wself1, const float* __restrict__ wneigh1,
                       const float* __restrict__ b1, const float* __restrict__ wcls,
                       const float* __restrict__ bcls) {
    int k = threadIdx.x;  // 0..255
    float a0 = 0.f, a1 = 0.f, s0 = 0.f, s1 = 0.f;
    for (int m = 0; m < D_HID; ++m) {
        float c0 = wcls[2 * m], c1 = wcls[2 * m + 1];
        float wn = wneigh1[k * D_HID + m];
        float ws = wself1[k * D_HID + m];
        a0 += wn * c0; a1 += wn * c1;
        s0 += ws * c0; s1 += ws * c1;
    }
    g_wn1c[2 * k] = a0; g_wn1c[2 * k + 1] = a1;
    g_ws1c[2 * k] = s0; g_ws1c[2 * k + 1] = s1;
    if (k < 2) {
        float acc = 0.f;
        for (int m = 0; m < D_HID; ++m) acc += b1[m] * wcls[2 * m + k];
        g_bc[k] = acc + bcls[k];
    }
}

// weight transposes for B operands (B[n,k] = W[k,n])
__global__ void k_trBp(const float* __restrict__ wpin, const float* __restrict__ wpout) {
    int idx = blockIdx.x * 256 + threadIdx.x;
    if (idx < 128 * 128) {
        int n = idx >> 7, k = idx & 127;
        g_Bp[idx] = (n < 64) ? wpin[k * 64 + n] : wpout[k * 64 + (n - 64)];
    }
}
__global__ void k_trBl(const float* __restrict__ wself, const float* __restrict__ wneigh) {
    int idx = blockIdx.x * 256 + threadIdx.x;
    if (idx < 256 * 384) {
        int n = idx / 384, k = idx - n * 384;
        g_Bl[idx] = (k < 192) ? wself[k * 256 + n] : wneigh[(k - 192) * 256 + n];
    }
}

// ---------------- prompt GEMM (mma.sync bf16 split x3): P = select(relu(X@[Wpin|Wpout]+b)) ----------------
// Block tile 128x128, 8 warps (4 row x 2 col), K=128 in 2 chunks of 64.
__global__ void __launch_bounds__(256) k_prompt_mma(
    const float* __restrict__ X, const void* __restrict__ mask,
    const float* __restrict__ bpin, const float* __restrict__ bpout) {
    extern __shared__ char sm_raw[];
    char* sm = (char*)(((uintptr_t)sm_raw + 1023) & ~(uintptr_t)1023);
    char* tAh = sm;
    char* tAl = tAh + 16384;
    char* tBh = tAl + 16384;
    char* tBl = tBh + 16384;
    int tid = threadIdx.x, wid = tid >> 5, lane = tid & 31;
    int rowWarp = wid & 3, colWarp = wid >> 2;
    int rowBase = blockIdx.x * 128;
    int mi = lane >> 3, ri = lane & 7;

    float C[2][8][4];
#pragma unroll
    for (int a = 0; a < 2; ++a)
#pragma unroll
        for (int b = 0; b < 8; ++b)
#pragma unroll
            for (int c = 0; c < 4; ++c) C[a][b][c] = 0.f;

    uint32_t uAh = smem_u32(tAh), uAl = smem_u32(tAl);
    uint32_t uBh = smem_u32(tBh), uBl = smem_u32(tBl);

    for (int kb = 0; kb < 2; ++kb) {
        fill_tile(tAh, tAl, X, 128, kb * 64, rowBase, N0, 128);
        fill_tile(tBh, tBl, g_Bp, 128, kb * 64, 0, 128, 128);
        __syncthreads();
#pragma unroll
        for (int k16 = 0; k16 < 4; ++k16) {
            int gA = k16 * 2 + (mi >> 1);
            uint32_t Ah[2][4], Al[2][4];
#pragma unroll
            for (int mf = 0; mf < 2; ++mf) {
                int r = rowWarp * 32 + mf * 16 + (mi & 1) * 8 + ri;
                ldm_x4(Ah[mf], tile_addr(uAh, r, gA));
                ldm_x4(Al[mf], tile_addr(uAl, r, gA));
            }
            uint32_t Bh[4][4], Bl[4][4];
#pragma unroll
            for (int q = 0; q < 4; ++q) {
                int n = colWarp * 64 + q * 16 + (mi & 1) * 8 + ri;
                ldm_x4(Bh[q], tile_addr(uBh, n, gA));
                ldm_x4(Bl[q], tile_addr(uBl, n, gA));
            }
#pragma unroll
            for (int mf = 0; mf < 2; ++mf)
#pragma unroll
                for (int j = 0; j < 8; ++j) {
                    int q = j >> 1, s = j & 1;
                    mma_bf16(C[mf][j], Ah[mf], Bh[q][s], Bh[q][s + 2]);
                    mma_bf16(C[mf][j], Ah[mf], Bl[q][s], Bl[q][s + 2]);
                    mma_bf16(C[mf][j], Al[mf], Bh[q][s], Bh[q][s + 2]);
                }
        }
        __syncthreads();
    }

    // epilogue: thread owns rows rq, rq+8 per mf; cols cq, cq+1 per n8 frag
    int rq = lane >> 2, cq = (lane & 3) * 2;
    int is8 = g_maskIs8;
#pragma unroll
    for (int mf = 0; mf < 2; ++mf) {
        int r0 = rowBase + rowWarp * 32 + mf * 16 + rq;
#pragma unroll
        for (int half = 0; half < 2; ++half) {
            int r = r0 + half * 8;
            if (r >= N0) continue;
            bool m = is8 ? (((const unsigned char*)mask)[r] != 0)
                         : (((const int*)mask)[r] != 0);
#pragma unroll
            for (int j = 0; j < 8; ++j) {
                int cn = colWarp * 64 + j * 8 + cq;
                bool keep = m ? (cn < 64) : (cn >= 64);
                if (keep) {
                    int cc = m ? cn : cn - 64;
                    const float* bp = m ? bpin : bpout;
                    float v0 = C[mf][j][half * 2 + 0] + bp[cc];
                    float v1 = C[mf][j][half * 2 + 1] + bp[cc + 1];
                    *(float2*)&g_P[(size_t)r * 64 + cc] =
                        make_float2(fmaxf(v0, 0.f), fmaxf(v1, 0.f));
                }
            }
        }
    }
}

// ---------------- layer0 CSR gather (f32) ----------------
__global__ void __launch_bounds__(256) k_gather0(const float* __restrict__ features) {
    int gw = (blockIdx.x * 256 + threadIdx.x) >> 5;
    int lane = threadIdx.x & 31;
    if (gw >= N1) return;
    int s0 = g_rowstart[gw], s1 = g_rowstart[gw + 1];
    const float4* F4 = (const float4*)features;
    const float2* P2 = (const float2*)g_P;
    float4 af = make_float4(0.f, 0.f, 0.f, 0.f);
    float2 ap = make_float2(0.f, 0.f);
    for (int t = s0; t < s1; ++t) {
        int s = g_esrc[t];
        float4 f = F4[(size_t)s * 32 + lane];
        af.x += f.x; af.y += f.y; af.z += f.z; af.w += f.w;
        float2 p = P2[(size_t)s * 32 + lane];
        ap.x += p.x; ap.y += p.y;
    }
    float inv = 1.0f / fmaxf((float)(s1 - s0), 1.0f);
    ((float4*)g_aggf)[(size_t)gw * 32 + lane] =
        make_float4(af.x * inv, af.y * inv, af.z * inv, af.w * inv);
    ((float2*)g_aggp)[(size_t)gw * 32 + lane] = make_float2(ap.x * inv, ap.y * inv);
}

// ---------------- layer0 GEMM (mma.sync bf16 split x3) + fused z1/selfc epilogue ----------------
// Block tile 128 rows x 256 cols (2 col-halves), K=384 in 6 chunks of 64.
__global__ void __launch_bounds__(256) k_layer0_mma(
    const float* __restrict__ features, const float* __restrict__ b0) {
    extern __shared__ char sm_raw[];
    char* sm = (char*)(((uintptr_t)sm_raw + 1023) & ~(uintptr_t)1023);
    char* tAh = sm;
    char* tAl = tAh + 16384;
    char* tBh = tAl + 16384;
    char* tBl = tBh + 32768;              // B tiles: 256 rows x 128B
    float* sB0 = (float*)(tBl + 32768);   // 256
    float* sWn = sB0 + 256;               // 512
    float* sWs = sWn + 512;               // 512
    float* zsm = sWs + 512;               // 128 rows x 4 vals
    int tid = threadIdx.x, wid = tid >> 5, lane = tid & 31;
    int rowWarp = wid & 3, colWarp = wid >> 2;
    int rowBase = blockIdx.x * 128;
    int mi = lane >> 3, ri = lane & 7;

    if (tid < 256) sB0[tid] = b0[tid];
    {
        int t2 = tid;
        sWn[t2] = g_wn1c[t2]; sWn[t2 + 256] = g_wn1c[t2 + 256];
        sWs[t2] = g_ws1c[t2]; sWs[t2 + 256] = g_ws1c[t2 + 256];
        if (t2 < 256) { zsm[t2] = 0.f; zsm[t2 + 256] = 0.f; }
    }

    float C[2][2][8][4];
#pragma unroll
    for (int a = 0; a < 2; ++a)
#pragma unroll
        for (int b = 0; b < 2; ++b)
#pragma unroll
            for (int c = 0; c < 8; ++c)
#pragma unroll
                for (int d = 0; d < 4; ++d) C[a][b][c][d] = 0.f;

    uint32_t uAh = smem_u32(tAh), uAl = smem_u32(tAl);
    uint32_t uBh = smem_u32(tBh), uBl = smem_u32(tBl);

    for (int kb = 0; kb < 6; ++kb) {
        const float* asrc;
        int astr, aofs;
        switch (kb) {
            case 0: asrc = features; astr = 128; aofs = 0;  break;
            case 1: asrc = features; astr = 128; aofs = 64; break;
            case 2: asrc = g_P;      astr = 64;  aofs = 0;  break;
            case 3: asrc = g_aggf;   astr = 128; aofs = 0;  break;
            case 4: asrc = g_aggf;   astr = 128; aofs = 64; break;
            default: asrc = g_aggp;  astr = 64;  aofs = 0;  break;
        }
        fill_tile(tAh, tAl, asrc, astr, aofs, rowBase, N1, 128);
        fill_tile(tBh, tBl, g_Bl, 384, kb * 64, 0, 256, 256);
        __syncthreads();
#pragma unroll
        for (int k16 = 0; k16 < 4; ++k16) {
            int gA = k16 * 2 + (mi >> 1);
            uint32_t Ah[2][4], Al[2][4];
#pragma unroll
            for (int mf = 0; mf < 2; ++mf) {
                int r = rowWarp * 32 + mf * 16 + (mi & 1) * 8 + ri;
                ldm_x4(Ah[mf], tile_addr(uAh, r, gA));
                ldm_x4(Al[mf], tile_addr(uAl, r, gA));
            }
#pragma unroll
            for (int nh = 0; nh < 2; ++nh) {
                uint32_t Bh[4][4], Bl[4][4];
#pragma unroll
                for (int q = 0; q < 4; ++q) {
                    int n = nh * 128 + colWarp * 64 + q * 16 + (mi & 1) * 8 + ri;
                    ldm_x4(Bh[q], tile_addr(uBh, n, gA));
                    ldm_x4(Bl[q], tile_addr(uBl, n, gA));
                }
#pragma unroll
                for (int mf = 0; mf < 2; ++mf)
#pragma unroll
                    for (int j = 0; j < 8; ++j) {
                        int q = j >> 1, s = j & 1;
                        mma_bf16(C[nh][mf][j], Ah[mf], Bh[q][s], Bh[q][s + 2]);
                        mma_bf16(C[nh][mf][j], Ah[mf], Bl[q][s], Bl[q][s + 2]);
                        mma_bf16(C[nh][mf][j], Al[mf], Bh[q][s], Bh[q][s + 2]);
                    }
            }
        }
        __syncthreads();
    }

    // fused epilogue: h = relu(C + b0); accumulate z = h@wn1c, s = h@ws1c per row
    int rq = lane >> 2, cq = (lane & 3) * 2;
    float za[2][2][4];  // [mf][rowhalf][z0,z1,s0,s1]
#pragma unroll
    for (int a = 0; a < 2; ++a)
#pragma unroll
        for (int b = 0; b < 2; ++b)
#pragma unroll
            for (int c = 0; c < 4; ++c) za[a][b][c] = 0.f;

#pragma unroll
    for (int nh = 0; nh < 2; ++nh)
#pragma unroll
        for (int mf = 0; mf < 2; ++mf)
#pragma unroll
            for (int j = 0; j < 8; ++j) {
                int cn = nh * 128 + colWarp * 64 + j * 8 + cq;
                float b0a = sB0[cn], b0b = sB0[cn + 1];
                float2 wna = *(const float2*)&sWn[2 * cn];
                float2 wnb = *(const float2*)&sWn[2 * cn + 2];
                float2 wsa = *(const float2*)&sWs[2 * cn];
                float2 wsb = *(const float2*)&sWs[2 * cn + 2];
#pragma unroll
                for (int half = 0; half < 2; ++half) {
                    float h0 = fmaxf(C[nh][mf][j][half * 2 + 0] + b0a, 0.f);
                    float h1 = fmaxf(C[nh][mf][j][half * 2 + 1] + b0b, 0.f);
                    za[mf][half][0] += h0 * wna.x + h1 * wnb.x;
                    za[mf][half][1] += h0 * wna.y + h1 * wnb.y;
                    za[mf][half][2] += h0 * wsa.x + h1 * wsb.x;
                    za[mf][half][3] += h0 * wsa.y + h1 * wsb.y;
                }
            }
    // quad reduce (lanes sharing a row) then smem combine across the 2 col-warps
#pragma unroll
    for (int mf = 0; mf < 2; ++mf)
#pragma unroll
        for (int half = 0; half < 2; ++half)
#pragma unroll
            for (int v = 0; v < 4; ++v) {
                float val = za[mf][half][v];
                val += __shfl_xor_sync(0xffffffffu, val, 1);
                val += __shfl_xor_sync(0xffffffffu, val, 2);
                if ((lane & 3) == 0) {
                    int rr = rowWarp * 32 + mf * 16 + half * 8 + rq;
                    atomicAdd(&zsm[rr * 4 + v], val);
                }
            }
    __syncthreads();
    if (tid < 128) {
        int r = rowBase + tid;
        if (r < N1) *(float2*)&g_z1[2 * r] = make_float2(zsm[tid * 4 + 0], zsm[tid * 4 + 1]);
        if (r < N2) *(float2*)&g_selfc[2 * r] = make_float2(zsm[tid * 4 + 2], zsm[tid * 4 + 3]);
    }
}

// ---------------- layer1 edge aggregation on z1 (2 floats/edge) ----------------
__global__ void k_edge1(const int* __restrict__ src1, const int* __restrict__ dst1) {
    int e = blockIdx.x * blockDim.x + threadIdx.x;
    if (e < E1) {
        int s = src1[e], d = dst1[e];
        atomicAdd(&g_z1acc[2 * d], g_z1[2 * s]);
        atomicAdd(&g_z1acc[2 * d + 1], g_z1[2 * s + 1]);
        atomicAdd(&g_deg1[d], 1.0f);
    }
}

// ---------------- final combine ----------------
__global__ void k_final(float* __restrict__ out) {
    int r = blockIdx.x * 256 + threadIdx.x;
    if (r < N2) {
        float inv = 1.0f / fmaxf(g_deg1[r], 1.0f);
        out[2 * r]     = g_selfc[2 * r]     + g_z1acc[2 * r] * inv     + g_bc[0];
        out[2 * r + 1] = g_selfc[2 * r + 1] + g_z1acc[2 * r + 1] * inv + g_bc[1];
    }
}

// ---------------- launch ----------------
extern "C" void kernel_launch(void* const* d_in, const int* in_sizes, int n_in,
                              void* d_out, int out_size) {
    const float* features = (const float*)d_in[0];
    const void* mask = d_in[1];
    const int* src0 = (const int*)d_in[2];
    const int* dst0 = (const int*)d_in[3];
    const int* src1 = (const int*)d_in[4];
    const int* dst1 = (const int*)d_in[5];
    // d_in[6] = output_nodes_indices (unused by reference)
    const float* w_pin = (const float*)d_in[7];
    const float* b_pin = (const float*)d_in[8];
    const float* w_pout = (const float*)d_in[9];
    const float* b_pout = (const float*)d_in[10];
    const float* w_self0 = (const float*)d_in[11];
    const float* w_neigh0 = (const float*)d_in[12];
    const float* b0 = (const float*)d_in[13];
    const float* w_self1 = (const float*)d_in[14];
    const float* w_neigh1 = (const float*)d_in[15];
    const float* b1 = (const float*)d_in[16];
    const float* w_cls = (const float*)d_in[17];
    const float* b_cls = (const float*)d_in[18];
    float* out = (float*)d_out;

    const int SMEM_P = 1024 + 4 * 16384;                                   // 66560
    const int SMEM_L = 1024 + 2 * 16384 + 2 * 32768 + (256 + 512 + 512 + 512) * 4;  // 106496
    cudaFuncSetAttribute(k_prompt_mma, cudaFuncAttributeMaxDynamicSharedMemorySize, SMEM_P);
    cudaFuncSetAttribute(k_layer0_mma, cudaFuncAttributeMaxDynamicSharedMemorySize, SMEM_L);

    k_zero<<<196, 256>>>();
    k_detect<<<(N0 / 4 + 255) / 256, 256>>>((const unsigned int*)mask);
    k_hist<<<E0 / 256, 256>>>(dst0);
    k_scan<<<1, 1024>>>();
    k_scatter<<<E0 / 256, 256>>>(src0, dst0);
    k_prep<<<1, 256>>>(w_self1, w_neigh1, b1, w_cls, b_cls);
    k_trBp<<<64, 256>>>(w_pin, w_pout);
    k_trBl<<<384, 256>>>(w_self0, w_neigh0);
    k_prompt_mma<<<(N0 + 127) / 128, 256, SMEM_P>>>(features, mask, b_pin, b_pout);
    k_gather0<<<N1 / 8, 256>>>(features);
    k_layer0_mma<<<(N1 + 127) / 128, 256, SMEM_L>>>(features, b0);
    k_edge1<<<E1 / 256, 256>>>(src1, dst1);
    k_final<<<(N2 + 255) / 256, 256>>>(out);
}

// round 7
// speedup vs baseline: 2.1340x; 1.1209x over previous
#include <cuda_runtime.h>
#include <cuda_bf16.h>
#include <math.h>
#include <stdint.h>

// Problem constants
#define N0 200000
#define N1 50000
#define N2 10000
#define D_IN 128
#define D_PROMPT 64
#define D_HID 256
#define E0 800000
#define E1 160000

// ---------------- scratch (static device globals; no allocation) ----------------
__device__ float g_P[N0 * D_PROMPT];         // selected prompt, relu'd   [200000,64]
__device__ float g_aggf[N1 * D_IN];          // mean-agg features (scaled)[50000,128]
__device__ float g_aggp[N1 * D_PROMPT];      // mean-agg prompt  (scaled) [50000,64]
__device__ float g_z1[N1 * 2];               // relu(H1) @ wn1c           [50000,2]
__device__ float g_selfc[N2 * 2];            // relu(H1)[:N2] @ ws1c      [10000,2]
__device__ float g_z1acc[N2 * 2];            // segment-sum of z1         [10000,2]
__device__ float g_deg1[N2];                 // layer1 in-degree
__device__ int   g_hist[N1];                 // layer0 in-degree histogram
__device__ int   g_rowstart[N1 + 1];         // CSR offsets
__device__ int   g_cursor[N1];               // scatter cursors
__device__ int   g_esrc[E0];                 // src node per CSR slot
__device__ int   g_bsum[64];                 // scan block sums
__device__ int   g_bofs[64];                 // scan block offsets
__device__ float g_wn1c[D_HID * 2];          // w_neigh1 @ w_cls
__device__ float g_ws1c[D_HID * 2];          // w_self1 @ w_cls
__device__ float g_bc[2];                    // b1 @ w_cls + b_cls
__device__ int   g_maskIs8;                  // 1 if mask is packed uint8, 0 if int32
__device__ float g_Bp[128 * 128];            // prompt B transposed: [n,k]; n<64 = wpin
__device__ float g_Bl[256 * 384];            // layer0 B transposed+stacked: [n,k]

// ================= mma.sync helpers (baseline PTX, no sm_103a gate) =================
__device__ __forceinline__ uint32_t smem_u32(const void* p) {
    return (uint32_t)__cvta_generic_to_shared(p);
}
__device__ __forceinline__ void ldm_x4(uint32_t* r, uint32_t addr) {
    asm volatile("ldmatrix.sync.aligned.m8n8.x4.shared.b16 {%0,%1,%2,%3}, [%4];"
                 : "=r"(r[0]), "=r"(r[1]), "=r"(r[2]), "=r"(r[3]) : "r"(addr));
}
__device__ __forceinline__ void mma_bf16(float* c, const uint32_t* a, uint32_t b0, uint32_t b1) {
    asm volatile(
        "mma.sync.aligned.m16n8k16.row.col.f32.bf16.bf16.f32 "
        "{%0,%1,%2,%3}, {%4,%5,%6,%7}, {%8,%9}, {%0,%1,%2,%3};"
        : "+f"(c[0]), "+f"(c[1]), "+f"(c[2]), "+f"(c[3])
        : "r"(a[0]), "r"(a[1]), "r"(a[2]), "r"(a[3]), "r"(b0), "r"(b1));
}
// tile rows = 128B (64 bf16), 16B granules XOR-swizzled by row
__device__ __forceinline__ uint32_t tile_addr(uint32_t base, int r, int g) {
    return base + (uint32_t)(r * 128) + (uint32_t)(((g ^ (r & 7)) << 4));
}

__device__ __forceinline__ uint32_t pack_bf2(__nv_bfloat16 a, __nv_bfloat16 b) {
    return ((uint32_t)__bfloat16_as_ushort(b) << 16) | (uint32_t)__bfloat16_as_ushort(a);
}
// fp32 -> (hi bf16, lo bf16) split tile fill; rows of 64 k-values (128B), swizzled
__device__ __forceinline__ void fill_tile(char* hi, char* lo,
                                          const float* __restrict__ src, int stride, int colOfs,
                                          int rowBase, int rowMax, int nRows) {
    for (int i = threadIdx.x; i < nRows * 8; i += 256) {
        int r = i >> 3, g = i & 7;
        int gr = rowBase + r;
        float4 v0 = make_float4(0.f, 0.f, 0.f, 0.f), v1 = v0;
        if (gr < rowMax) {
            const float* p = &src[(size_t)gr * stride + colOfs + g * 8];
            v0 = *(const float4*)p;
            v1 = *(const float4*)(p + 4);
        }
        __nv_bfloat16 h0 = __float2bfloat16_rn(v0.x), h1 = __float2bfloat16_rn(v0.y);
        __nv_bfloat16 h2 = __float2bfloat16_rn(v0.z), h3 = __float2bfloat16_rn(v0.w);
        __nv_bfloat16 h4 = __float2bfloat16_rn(v1.x), h5 = __float2bfloat16_rn(v1.y);
        __nv_bfloat16 h6 = __float2bfloat16_rn(v1.z), h7 = __float2bfloat16_rn(v1.w);
        uint4 H, L;
        H.x = pack_bf2(h0, h1); H.y = pack_bf2(h2, h3);
        H.z = pack_bf2(h4, h5); H.w = pack_bf2(h6, h7);
        L.x = pack_bf2(__float2bfloat16_rn(v0.x - __bfloat162float(h0)),
                       __float2bfloat16_rn(v0.y - __bfloat162float(h1)));
        L.y = pack_bf2(__float2bfloat16_rn(v0.z - __bfloat162float(h2)),
                       __float2bfloat16_rn(v0.w - __bfloat162float(h3)));
        L.z = pack_bf2(__float2bfloat16_rn(v1.x - __bfloat162float(h4)),
                       __float2bfloat16_rn(v1.y - __bfloat162float(h5)));
        L.w = pack_bf2(__float2bfloat16_rn(v1.z - __bfloat162float(h6)),
                       __float2bfloat16_rn(v1.w - __bfloat162float(h7)));
        uint32_t off = (uint32_t)(r * 128) + (uint32_t)(((g ^ (r & 7)) << 4));
        *(uint4*)(hi + off) = H;
        *(uint4*)(lo + off) = L;
    }
}

// ---------------- small utility kernels ----------------
__global__ void k_zero() {
    int i = blockIdx.x * blockDim.x + threadIdx.x;
    if (i < N1) g_hist[i] = 0;
    if (i < N2 * 2) g_z1acc[i] = 0.0f;
    if (i < N2) g_deg1[i] = 0.0f;
    if (i == 0) g_maskIs8 = 0;
}

__global__ void k_detect(const unsigned int* __restrict__ maskw) {
    int i = blockIdx.x * blockDim.x + threadIdx.x;
    if (i < N0 / 4) {
        if (maskw[i] > 1u) atomicOr(&g_maskIs8, 1);
    }
}

__global__ void k_hist(const int* __restrict__ dst0) {
    int e = blockIdx.x * blockDim.x + threadIdx.x;
    if (e < E0) atomicAdd(&g_hist[dst0[e]], 1);
}

// ---- parallel scan, 3 phases ----
// A: 49 blocks x 1024; block-local exclusive scan of g_hist -> g_rowstart, block total -> g_bsum
__global__ void __launch_bounds__(1024) k_scanA() {
    int tid = threadIdx.x, lane = tid & 31, w = tid >> 5;
    int idx = blockIdx.x * 1024 + tid;
    int val = (idx < N1) ? g_hist[idx] : 0;
    int v = val;
#pragma unroll
    for (int off = 1; off < 32; off <<= 1) {
        int t = __shfl_up_sync(0xffffffffu, v, off);
        if (lane >= off) v += t;
    }
    __shared__ int wsum[32];
    if (lane == 31) wsum[w] = v;
    __syncthreads();
    if (w == 0) {
        int x = wsum[lane];
#pragma unroll
        for (int off = 1; off < 32; off <<= 1) {
            int t = __shfl_up_sync(0xffffffffu, x, off);
            if (lane >= off) x += t;
        }
        wsum[lane] = x;
    }
    __syncthreads();
    int incl = v + (w ? wsum[w - 1] : 0);
    if (idx < N1) g_rowstart[idx] = incl - val;  // local exclusive
    if (tid == 1023) g_bsum[blockIdx.x] = incl;
}
// B: single thread scans 49 block sums
__global__ void k_scanB() {
    int run = 0;
    for (int b = 0; b < 49; ++b) {
        g_bofs[b] = run;
        run += g_bsum[b];
    }
    g_rowstart[N1] = run;
}
// C: add block offsets, init cursors
__global__ void __launch_bounds__(1024) k_scanC() {
    int idx = blockIdx.x * 1024 + threadIdx.x;
    if (idx < N1) {
        int rs = g_rowstart[idx] + g_bofs[blockIdx.x];
        g_rowstart[idx] = rs;
        g_cursor[idx] = rs;
    }
}

__global__ void k_scatter(const int* __restrict__ src0, const int* __restrict__ dst0) {
    int e = blockIdx.x * blockDim.x + threadIdx.x;
    if (e < E0) {
        int pos = atomicAdd(&g_cursor[dst0[e]], 1);
        g_esrc[pos] = src0[e];
    }
}

// fold layer1 + classifier weights
__global__ void k_prep(const float* __restrict__ wself1, const float* __restrict__ wneigh1,
                       const float* __restrict__ b1, const float* __restrict__ wcls,
                       const float* __restrict__ bcls) {
    int k = threadIdx.x;  // 0..255
    float a0 = 0.f, a1 = 0.f, s0 = 0.f, s1 = 0.f;
    for (int m = 0; m < D_HID; ++m) {
        float c0 = wcls[2 * m], c1 = wcls[2 * m + 1];
        float wn = wneigh1[k * D_HID + m];
        float ws = wself1[k * D_HID + m];
        a0 += wn * c0; a1 += wn * c1;
        s0 += ws * c0; s1 += ws * c1;
    }
    g_wn1c[2 * k] = a0; g_wn1c[2 * k + 1] = a1;
    g_ws1c[2 * k] = s0; g_ws1c[2 * k + 1] = s1;
    if (k < 2) {
        float acc = 0.f;
        for (int m = 0; m < D_HID; ++m) acc += b1[m] * wcls[2 * m + k];
        g_bc[k] = acc + bcls[k];
    }
}

// weight transposes for B operands (B[n,k] = W[k,n])
__global__ void k_trBp(const float* __restrict__ wpin, const float* __restrict__ wpout) {
    int idx = blockIdx.x * 256 + threadIdx.x;
    if (idx < 128 * 128) {
        int n = idx >> 7, k = idx & 127;
        g_Bp[idx] = (n < 64) ? wpin[k * 64 + n] : wpout[k * 64 + (n - 64)];
    }
}
__global__ void k_trBl(const float* __restrict__ wself, const float* __restrict__ wneigh) {
    int idx = blockIdx.x * 256 + threadIdx.x;
    if (idx < 256 * 384) {
        int n = idx / 384, k = idx - n * 384;
        g_Bl[idx] = (k < 192) ? wself[k * 256 + n] : wneigh[(k - 192) * 256 + n];
    }
}

// ---------------- prompt GEMM (mma.sync bf16 split x3): P = select(relu(X@[Wpin|Wpout]+b)) ----------------
// Block tile 128x128, 8 warps (4 row x 2 col), K=128 in 2 chunks of 64.
__global__ void __launch_bounds__(256) k_prompt_mma(
    const float* __restrict__ X, const void* __restrict__ mask,
    const float* __restrict__ bpin, const float* __restrict__ bpout) {
    extern __shared__ char sm_raw[];
    char* sm = (char*)(((uintptr_t)sm_raw + 1023) & ~(uintptr_t)1023);
    char* tAh = sm;
    char* tAl = tAh + 16384;
    char* tBh = tAl + 16384;
    char* tBl = tBh + 16384;
    int tid = threadIdx.x, wid = tid >> 5, lane = tid & 31;
    int rowWarp = wid & 3, colWarp = wid >> 2;
    int rowBase = blockIdx.x * 128;
    int mi = lane >> 3, ri = lane & 7;

    float C[2][8][4];
#pragma unroll
    for (int a = 0; a < 2; ++a)
#pragma unroll
        for (int b = 0; b < 8; ++b)
#pragma unroll
            for (int c = 0; c < 4; ++c) C[a][b][c] = 0.f;

    uint32_t uAh = smem_u32(tAh), uAl = smem_u32(tAl);
    uint32_t uBh = smem_u32(tBh), uBl = smem_u32(tBl);

    for (int kb = 0; kb < 2; ++kb) {
        fill_tile(tAh, tAl, X, 128, kb * 64, rowBase, N0, 128);
        fill_tile(tBh, tBl, g_Bp, 128, kb * 64, 0, 128, 128);
        __syncthreads();
#pragma unroll
        for (int k16 = 0; k16 < 4; ++k16) {
            int gA = k16 * 2 + (mi >> 1);
            uint32_t Ah[2][4], Al[2][4];
#pragma unroll
            for (int mf = 0; mf < 2; ++mf) {
                int r = rowWarp * 32 + mf * 16 + (mi & 1) * 8 + ri;
                ldm_x4(Ah[mf], tile_addr(uAh, r, gA));
                ldm_x4(Al[mf], tile_addr(uAl, r, gA));
            }
            uint32_t Bh[4][4], Bl[4][4];
#pragma unroll
            for (int q = 0; q < 4; ++q) {
                int n = colWarp * 64 + q * 16 + (mi & 1) * 8 + ri;
                ldm_x4(Bh[q], tile_addr(uBh, n, gA));
                ldm_x4(Bl[q], tile_addr(uBl, n, gA));
            }
#pragma unroll
            for (int mf = 0; mf < 2; ++mf)
#pragma unroll
                for (int j = 0; j < 8; ++j) {
                    int q = j >> 1, s = j & 1;
                    mma_bf16(C[mf][j], Ah[mf], Bh[q][s], Bh[q][s + 2]);
                    mma_bf16(C[mf][j], Ah[mf], Bl[q][s], Bl[q][s + 2]);
                    mma_bf16(C[mf][j], Al[mf], Bh[q][s], Bh[q][s + 2]);
                }
        }
        __syncthreads();
    }

    // epilogue: thread owns rows rq, rq+8 per mf; cols cq, cq+1 per n8 frag
    int rq = lane >> 2, cq = (lane & 3) * 2;
    int is8 = g_maskIs8;
#pragma unroll
    for (int mf = 0; mf < 2; ++mf) {
        int r0 = rowBase + rowWarp * 32 + mf * 16 + rq;
#pragma unroll
        for (int half = 0; half < 2; ++half) {
            int r = r0 + half * 8;
            if (r >= N0) continue;
            bool m = is8 ? (((const unsigned char*)mask)[r] != 0)
                         : (((const int*)mask)[r] != 0);
#pragma unroll
            for (int j = 0; j < 8; ++j) {
                int cn = colWarp * 64 + j * 8 + cq;
                bool keep = m ? (cn < 64) : (cn >= 64);
                if (keep) {
                    int cc = m ? cn : cn - 64;
                    const float* bp = m ? bpin : bpout;
                    float v0 = C[mf][j][half * 2 + 0] + bp[cc];
                    float v1 = C[mf][j][half * 2 + 1] + bp[cc + 1];
                    *(float2*)&g_P[(size_t)r * 64 + cc] =
                        make_float2(fmaxf(v0, 0.f), fmaxf(v1, 0.f));
                }
            }
        }
    }
}

// ---------------- layer0 CSR gather (f32), 4x unrolled for MLP ----------------
__global__ void __launch_bounds__(256) k_gather0(const float* __restrict__ features) {
    int gw = (blockIdx.x * 256 + threadIdx.x) >> 5;
    int lane = threadIdx.x & 31;
    if (gw >= N1) return;
    int s0 = g_rowstart[gw], s1 = g_rowstart[gw + 1];
    const float4* F4 = (const float4*)features;
    const float2* P2 = (const float2*)g_P;
    float4 af = make_float4(0.f, 0.f, 0.f, 0.f);
    float2 ap = make_float2(0.f, 0.f);
    int t = s0;
    for (; t + 4 <= s1; t += 4) {
        int i0 = g_esrc[t], i1 = g_esrc[t + 1], i2 = g_esrc[t + 2], i3 = g_esrc[t + 3];
        float4 f0 = F4[(size_t)i0 * 32 + lane];
        float4 f1 = F4[(size_t)i1 * 32 + lane];
        float4 f2 = F4[(size_t)i2 * 32 + lane];
        float4 f3 = F4[(size_t)i3 * 32 + lane];
        float2 p0 = P2[(size_t)i0 * 32 + lane];
        float2 p1 = P2[(size_t)i1 * 32 + lane];
        float2 p2 = P2[(size_t)i2 * 32 + lane];
        float2 p3 = P2[(size_t)i3 * 32 + lane];
        af.x += (f0.x + f1.x) + (f2.x + f3.x);
        af.y += (f0.y + f1.y) + (f2.y + f3.y);
        af.z += (f0.z + f1.z) + (f2.z + f3.z);
        af.w += (f0.w + f1.w) + (f2.w + f3.w);
        ap.x += (p0.x + p1.x) + (p2.x + p3.x);
        ap.y += (p0.y + p1.y) + (p2.y + p3.y);
    }
    for (; t < s1; ++t) {
        int s = g_esrc[t];
        float4 f = F4[(size_t)s * 32 + lane];
        af.x += f.x; af.y += f.y; af.z += f.z; af.w += f.w;
        float2 p = P2[(size_t)s * 32 + lane];
        ap.x += p.x; ap.y += p.y;
    }
    float inv = 1.0f / fmaxf((float)(s1 - s0), 1.0f);
    ((float4*)g_aggf)[(size_t)gw * 32 + lane] =
        make_float4(af.x * inv, af.y * inv, af.z * inv, af.w * inv);
    ((float2*)g_aggp)[(size_t)gw * 32 + lane] = make_float2(ap.x * inv, ap.y * inv);
}

// ---------------- layer0 GEMM (mma.sync bf16 split x3) + fused z1/selfc epilogue ----------------
// Block tile 128 rows x 256 cols (2 col-halves), K=384 in 6 chunks of 64.
__global__ void __launch_bounds__(256) k_layer0_mma(
    const float* __restrict__ features, const float* __restrict__ b0) {
    extern __shared__ char sm_raw[];
    char* sm = (char*)(((uintptr_t)sm_raw + 1023) & ~(uintptr_t)1023);
    char* tAh = sm;
    char* tAl = tAh + 16384;
    char* tBh = tAl + 16384;
    char* tBl = tBh + 32768;              // B tiles: 256 rows x 128B
    float* sB0 = (float*)(tBl + 32768);   // 256
    float* sWn = sB0 + 256;               // 512
    float* sWs = sWn + 512;               // 512
    float* zsm = sWs + 512;               // 128 rows x 4 vals
    int tid = threadIdx.x, wid = tid >> 5, lane = tid & 31;
    int rowWarp = wid & 3, colWarp = wid >> 2;
    int rowBase = blockIdx.x * 128;
    int mi = lane >> 3, ri = lane & 7;

    if (tid < 256) sB0[tid] = b0[tid];
    {
        int t2 = tid;
        sWn[t2] = g_wn1c[t2]; sWn[t2 + 256] = g_wn1c[t2 + 256];
        sWs[t2] = g_ws1c[t2]; sWs[t2 + 256] = g_ws1c[t2 + 256];
        if (t2 < 256) { zsm[t2] = 0.f; zsm[t2 + 256] = 0.f; }
    }

    float C[2][2][8][4];
#pragma unroll
    for (int a = 0; a < 2; ++a)
#pragma unroll
        for (int b = 0; b < 2; ++b)
#pragma unroll
            for (int c = 0; c < 8; ++c)
#pragma unroll
                for (int d = 0; d < 4; ++d) C[a][b][c][d] = 0.f;

    uint32_t uAh = smem_u32(tAh), uAl = smem_u32(tAl);
    uint32_t uBh = smem_u32(tBh), uBl = smem_u32(tBl);

    for (int kb = 0; kb < 6; ++kb) {
        const float* asrc;
        int astr, aofs;
        switch (kb) {
            case 0: asrc = features; astr = 128; aofs = 0;  break;
            case 1: asrc = features; astr = 128; aofs = 64; break;
            case 2: asrc = g_P;      astr = 64;  aofs = 0;  break;
            case 3: asrc = g_aggf;   astr = 128; aofs = 0;  break;
            case 4: asrc = g_aggf;   astr = 128; aofs = 64; break;
            default: asrc = g_aggp;  astr = 64;  aofs = 0;  break;
        }
        fill_tile(tAh, tAl, asrc, astr, aofs, rowBase, N1, 128);
        fill_tile(tBh, tBl, g_Bl, 384, kb * 64, 0, 256, 256);
        __syncthreads();
#pragma unroll
        for (int k16 = 0; k16 < 4; ++k16) {
            int gA = k16 * 2 + (mi >> 1);
            uint32_t Ah[2][4], Al[2][4];
#pragma unroll
            for (int mf = 0; mf < 2; ++mf) {
                int r = rowWarp * 32 + mf * 16 + (mi & 1) * 8 + ri;
                ldm_x4(Ah[mf], tile_addr(uAh, r, gA));
                ldm_x4(Al[mf], tile_addr(uAl, r, gA));
            }
#pragma unroll
            for (int nh = 0; nh < 2; ++nh) {
                uint32_t Bh[4][4], Bl[4][4];
#pragma unroll
                for (int q = 0; q < 4; ++q) {
                    int n = nh * 128 + colWarp * 64 + q * 16 + (mi & 1) * 8 + ri;
                    ldm_x4(Bh[q], tile_addr(uBh, n, gA));
                    ldm_x4(Bl[q], tile_addr(uBl, n, gA));
                }
#pragma unroll
                for (int mf = 0; mf < 2; ++mf)
#pragma unroll
                    for (int j = 0; j < 8; ++j) {
                        int q = j >> 1, s = j & 1;
                        mma_bf16(C[nh][mf][j], Ah[mf], Bh[q][s], Bh[q][s + 2]);
                        mma_bf16(C[nh][mf][j], Ah[mf], Bl[q][s], Bl[q][s + 2]);
                        mma_bf16(C[nh][mf][j], Al[mf], Bh[q][s], Bh[q][s + 2]);
                    }
            }
        }
        __syncthreads();
    }

    // fused epilogue: h = relu(C + b0); accumulate z = h@wn1c, s = h@ws1c per row
    int rq = lane >> 2, cq = (lane & 3) * 2;
    float za[2][2][4];  // [mf][rowhalf][z0,z1,s0,s1]
#pragma unroll
    for (int a = 0; a < 2; ++a)
#pragma unroll
        for (int b = 0; b < 2; ++b)
#pragma unroll
            for (int c = 0; c < 4; ++c) za[a][b][c] = 0.f;

#pragma unroll
    for (int nh = 0; nh < 2; ++nh)
#pragma unroll
        for (int mf = 0; mf < 2; ++mf)
#pragma unroll
            for (int j = 0; j < 8; ++j) {
                int cn = nh * 128 + colWarp * 64 + j * 8 + cq;
                float b0a = sB0[cn], b0b = sB0[cn + 1];
                float2 wna = *(const float2*)&sWn[2 * cn];
                float2 wnb = *(const float2*)&sWn[2 * cn + 2];
                float2 wsa = *(const float2*)&sWs[2 * cn];
                float2 wsb = *(const float2*)&sWs[2 * cn + 2];
#pragma unroll
                for (int half = 0; half < 2; ++half) {
                    float h0 = fmaxf(C[nh][mf][j][half * 2 + 0] + b0a, 0.f);
                    float h1 = fmaxf(C[nh][mf][j][half * 2 + 1] + b0b, 0.f);
                    za[mf][half][0] += h0 * wna.x + h1 * wnb.x;
                    za[mf][half][1] += h0 * wna.y + h1 * wnb.y;
                    za[mf][half][2] += h0 * wsa.x + h1 * wsb.x;
                    za[mf][half][3] += h0 * wsa.y + h1 * wsb.y;
                }
            }
    // quad reduce (lanes sharing a row) then smem combine across the 2 col-warps
#pragma unroll
    for (int mf = 0; mf < 2; ++mf)
#pragma unroll
        for (int half = 0; half < 2; ++half)
#pragma unroll
            for (int v = 0; v < 4; ++v) {
                float val = za[mf][half][v];
                val += __shfl_xor_sync(0xffffffffu, val, 1);
                val += __shfl_xor_sync(0xffffffffu, val, 2);
                if ((lane & 3) == 0) {
                    int rr = rowWarp * 32 + mf * 16 + half * 8 + rq;
                    atomicAdd(&zsm[rr * 4 + v], val);
                }
            }
    __syncthreads();
    if (tid < 128) {
        int r = rowBase + tid;
        if (r < N1) *(float2*)&g_z1[2 * r] = make_float2(zsm[tid * 4 + 0], zsm[tid * 4 + 1]);
        if (r < N2) *(float2*)&g_selfc[2 * r] = make_float2(zsm[tid * 4 + 2], zsm[tid * 4 + 3]);
    }
}

// ---------------- layer1 edge aggregation on z1 (2 floats/edge) ----------------
__global__ void k_edge1(const int* __restrict__ src1, const int* __restrict__ dst1) {
    int e = blockIdx.x * blockDim.x + threadIdx.x;
    if (e < E1) {
        int s = src1[e], d = dst1[e];
        atomicAdd(&g_z1acc[2 * d], g_z1[2 * s]);
        atomicAdd(&g_z1acc[2 * d + 1], g_z1[2 * s + 1]);
        atomicAdd(&g_deg1[d], 1.0f);
    }
}

// ---------------- final combine ----------------
__global__ void k_final(float* __restrict__ out) {
    int r = blockIdx.x * 256 + threadIdx.x;
    if (r < N2) {
        float inv = 1.0f / fmaxf(g_deg1[r], 1.0f);
        out[2 * r]     = g_selfc[2 * r]     + g_z1acc[2 * r] * inv     + g_bc[0];
        out[2 * r + 1] = g_selfc[2 * r + 1] + g_z1acc[2 * r + 1] * inv + g_bc[1];
    }
}

// ---------------- launch ----------------
extern "C" void kernel_launch(void* const* d_in, const int* in_sizes, int n_in,
                              void* d_out, int out_size) {
    const float* features = (const float*)d_in[0];
    const void* mask = d_in[1];
    const int* src0 = (const int*)d_in[2];
    const int* dst0 = (const int*)d_in[3];
    const int* src1 = (const int*)d_in[4];
    const int* dst1 = (const int*)d_in[5];
    // d_in[6] = output_nodes_indices (unused by reference)
    const float* w_pin = (const float*)d_in[7];
    const float* b_pin = (const float*)d_in[8];
    const float* w_pout = (const float*)d_in[9];
    const float* b_pout = (const float*)d_in[10];
    const float* w_self0 = (const float*)d_in[11];
    const float* w_neigh0 = (const float*)d_in[12];
    const float* b0 = (const float*)d_in[13];
    const float* w_self1 = (const float*)d_in[14];
    const float* w_neigh1 = (const float*)d_in[15];
    const float* b1 = (const float*)d_in[16];
    const float* w_cls = (const float*)d_in[17];
    const float* b_cls = (const float*)d_in[18];
    float* out = (float*)d_out;

    const int SMEM_P = 1024 + 4 * 16384;                                   // 66560
    const int SMEM_L = 1024 + 2 * 16384 + 2 * 32768 + (256 + 512 + 512 + 512) * 4;  // 106496
    cudaFuncSetAttribute(k_prompt_mma, cudaFuncAttributeMaxDynamicSharedMemorySize, SMEM_P);
    cudaFuncSetAttribute(k_layer0_mma, cudaFuncAttributeMaxDynamicSharedMemorySize, SMEM_L);

    k_zero<<<196, 256>>>();
    k_detect<<<(N0 / 4 + 255) / 256, 256>>>((const unsigned int*)mask);
    k_hist<<<E0 / 256, 256>>>(dst0);
    k_scanA<<<49, 1024>>>();
    k_scanB<<<1, 1>>>();
    k_scanC<<<49, 1024>>>();
    k_scatter<<<E0 / 256, 256>>>(src0, dst0);
    k_prep<<<1, 256>>>(w_self1, w_neigh1, b1, w_cls, b_cls);
    k_trBp<<<64, 256>>>(w_pin, w_pout);
    k_trBl<<<384, 256>>>(w_self0, w_neigh0);
    k_prompt_mma<<<(N0 + 127) / 128, 256, SMEM_P>>>(features, mask, b_pin, b_pout);
    k_gather0<<<N1 / 8, 256>>>(features);
    k_layer0_mma<<<(N1 + 127) / 128, 256, SMEM_L>>>(features, b0);
    k_edge1<<<E1 / 256, 256>>>(src1, dst1);
    k_final<<<(N2 + 255) / 256, 256>>>(out);
}